// round 1
// baseline (speedup 1.0000x reference)
#include <cuda_runtime.h>
#include <cuda_bf16.h>

#define B_SIZE 16384
#define K_NEG  20
#define DIM    128

__global__ void zero_out_kernel(float* out, int n) {
    for (int i = threadIdx.x; i < n; i += blockDim.x) out[i] = 0.0f;
}

__device__ __forceinline__ float warp_sum(float v) {
    v += __shfl_xor_sync(0xffffffffu, v, 16);
    v += __shfl_xor_sync(0xffffffffu, v, 8);
    v += __shfl_xor_sync(0xffffffffu, v, 4);
    v += __shfl_xor_sync(0xffffffffu, v, 2);
    v += __shfl_xor_sync(0xffffffffu, v, 1);
    return v;
}

// Numerically stable log(sigmoid(x)) = min(x,0) - log1p(exp(-|x|))
__device__ __forceinline__ float log_sigmoid(float x) {
    return fminf(x, 0.0f) - log1pf(__expf(-fabsf(x)));
}

__global__ __launch_bounds__(256) void skipgram_kernel(
    const int* __restrict__ target,
    const int* __restrict__ context,
    const int* __restrict__ negs,
    const float* __restrict__ in_embed,
    const float* __restrict__ out_embed,
    float* __restrict__ out)
{
    const int lane = threadIdx.x & 31;
    const int warp_in_block = threadIdx.x >> 5;
    const int b = blockIdx.x * (blockDim.x >> 5) + warp_in_block;

    float loss = 0.0f;
    if (b < B_SIZE) {
        // Each lane owns 4 consecutive floats of the 128-float row (fully coalesced).
        const float4 tv = reinterpret_cast<const float4*>(
            in_embed + (size_t)__ldg(target + b) * DIM)[lane];

        // Positive score
        {
            const float4 cv = reinterpret_cast<const float4*>(
                out_embed + (size_t)__ldg(context + b) * DIM)[lane];
            float p = tv.x * cv.x + tv.y * cv.y + tv.z * cv.z + tv.w * cv.w;
            p = warp_sum(p);
            loss = log_sigmoid(p);
        }

        // Negative scores
        const int* nb = negs + (size_t)b * K_NEG;
        #pragma unroll 5
        for (int k = 0; k < K_NEG; k++) {
            const float4 nv = reinterpret_cast<const float4*>(
                out_embed + (size_t)__ldg(nb + k) * DIM)[lane];
            float s = tv.x * nv.x + tv.y * nv.y + tv.z * nv.z + tv.w * nv.w;
            s = warp_sum(s);
            loss += log_sigmoid(-s);
        }
    }

    // Block reduction: lane 0 of each warp contributes its row loss.
    __shared__ float smem[8];
    if (lane == 0) smem[warp_in_block] = loss;
    __syncthreads();

    if (threadIdx.x == 0) {
        float acc = 0.0f;
        const int nwarps = blockDim.x >> 5;
        #pragma unroll
        for (int w = 0; w < 8; w++)
            if (w < nwarps) acc += smem[w];
        // final result = -(mean(pos_loss) + mean(neg_loss)) = -sum(loss_b)/B
        atomicAdd(out, -acc * (1.0f / (float)B_SIZE));
    }
}

extern "C" void kernel_launch(void* const* d_in, const int* in_sizes, int n_in,
                              void* d_out, int out_size) {
    const int*   target    = (const int*)d_in[0];
    const int*   context   = (const int*)d_in[1];
    const int*   negs      = (const int*)d_in[2];
    const float* in_embed  = (const float*)d_in[3];
    const float* out_embed = (const float*)d_in[4];
    float*       out       = (float*)d_out;

    zero_out_kernel<<<1, 32>>>(out, out_size);

    // 8 warps per block, one batch row per warp.
    const int warps_per_block = 8;
    const int blocks = (B_SIZE + warps_per_block - 1) / warps_per_block; // 2048
    skipgram_kernel<<<blocks, warps_per_block * 32>>>(
        target, context, negs, in_embed, out_embed, out);
}

// round 2
// speedup vs baseline: 1.4100x; 1.4100x over previous
#include <cuda_runtime.h>
#include <cuda_bf16.h>

#define B_SIZE 16384
#define K_NEG  20
#define DIM    128

__global__ void zero_out_kernel(float* out, int n) {
    for (int i = threadIdx.x; i < n; i += blockDim.x) out[i] = 0.0f;
}

__device__ __forceinline__ float warp_sum(float v) {
    v += __shfl_xor_sync(0xffffffffu, v, 16);
    v += __shfl_xor_sync(0xffffffffu, v, 8);
    v += __shfl_xor_sync(0xffffffffu, v, 4);
    v += __shfl_xor_sync(0xffffffffu, v, 2);
    v += __shfl_xor_sync(0xffffffffu, v, 1);
    return v;
}

// Fast, stable log(sigmoid(x)) = min(x,0) - log(1 + exp(-|x|))
__device__ __forceinline__ float log_sigmoid_fast(float x) {
    return fminf(x, 0.0f) - __logf(1.0f + __expf(-fabsf(x)));
}

__global__ __launch_bounds__(256) void skipgram_kernel(
    const int* __restrict__ target,
    const int* __restrict__ context,
    const int* __restrict__ negs,
    const float* __restrict__ in_embed,
    const float* __restrict__ out_embed,
    float* __restrict__ out)
{
    const int lane = threadIdx.x & 31;
    const int warp_in_block = threadIdx.x >> 5;
    const int b = blockIdx.x * (blockDim.x >> 5) + warp_in_block;

    float contrib = 0.0f;
    if (b < B_SIZE) {
        // Each lane owns 4 consecutive floats of the 128-float row.
        const float4 tv = reinterpret_cast<const float4*>(
            in_embed + (size_t)__ldg(target + b) * DIM)[lane];

        // v[k] = this lane's partial dot for value k.
        // k in [0,20) : negative scores; k == 20 : positive score; k > 20 : zero pad.
        float v[32];
        #pragma unroll
        for (int j = 21; j < 32; j++) v[j] = 0.0f;

        {
            const float4 cv = reinterpret_cast<const float4*>(
                out_embed + (size_t)__ldg(context + b) * DIM)[lane];
            v[20] = tv.x * cv.x + tv.y * cv.y + tv.z * cv.z + tv.w * cv.w;
        }

        const int* nb = negs + (size_t)b * K_NEG;
        #pragma unroll
        for (int k = 0; k < K_NEG; k++) {
            const float4 nv = reinterpret_cast<const float4*>(
                out_embed + (size_t)__ldg(nb + k) * DIM)[lane];
            v[k] = tv.x * nv.x + tv.y * nv.y + tv.z * nv.z + tv.w * nv.w;
        }

        // Packed butterfly transpose-reduce: after 5 stages, v[0] on lane L
        // holds the fully lane-summed value L. 31 shuffles total (vs 105 naive).
        #pragma unroll
        for (int i = 0; i < 5; i++) {
            const int off = 1 << i;
            const bool par = (lane >> i) & 1;   // keep odd-slot values if set
            const int n = 32 >> i;
            #pragma unroll
            for (int j = 0; j < n / 2; j++) {
                const float a = v[2 * j];
                const float c = v[2 * j + 1];
                const float send = par ? a : c;
                const float keep = par ? c : a;
                const float got = __shfl_xor_sync(0xffffffffu, send, off);
                v[j] = keep + got;
            }
        }

        const float s = v[0];                    // score for index == lane
        const float x = (lane == 20) ? s : -s;   // pos uses +s, negs use -s
        if (lane <= 20) contrib = log_sigmoid_fast(x);
    }

    // Sum the 21 per-lane loss terms of this row, then block-reduce.
    contrib = warp_sum(contrib);

    __shared__ float smem[8];
    if (lane == 0) smem[warp_in_block] = contrib;
    __syncthreads();

    if (threadIdx.x == 0) {
        float acc = 0.0f;
        const int nwarps = blockDim.x >> 5;
        #pragma unroll
        for (int w = 0; w < 8; w++)
            if (w < nwarps) acc += smem[w];
        atomicAdd(out, -acc * (1.0f / (float)B_SIZE));
    }
}

extern "C" void kernel_launch(void* const* d_in, const int* in_sizes, int n_in,
                              void* d_out, int out_size) {
    const int*   target    = (const int*)d_in[0];
    const int*   context   = (const int*)d_in[1];
    const int*   negs      = (const int*)d_in[2];
    const float* in_embed  = (const float*)d_in[3];
    const float* out_embed = (const float*)d_in[4];
    float*       out       = (float*)d_out;

    zero_out_kernel<<<1, 32>>>(out, out_size);

    const int warps_per_block = 8;
    const int blocks = (B_SIZE + warps_per_block - 1) / warps_per_block; // 2048
    skipgram_kernel<<<blocks, warps_per_block * 32>>>(
        target, context, negs, in_embed, out_embed, out);
}

// round 3
// speedup vs baseline: 1.6053x; 1.1385x over previous
#include <cuda_runtime.h>
#include <cuda_bf16.h>

#define B_SIZE 16384
#define K_NEG  20
#define DIM    128

__global__ void zero_out_kernel(float* out, int n) {
    for (int i = threadIdx.x; i < n; i += blockDim.x) out[i] = 0.0f;
}

__device__ __forceinline__ float warp_sum(float v) {
    v += __shfl_xor_sync(0xffffffffu, v, 16);
    v += __shfl_xor_sync(0xffffffffu, v, 8);
    v += __shfl_xor_sync(0xffffffffu, v, 4);
    v += __shfl_xor_sync(0xffffffffu, v, 2);
    v += __shfl_xor_sync(0xffffffffu, v, 1);
    return v;
}

// Fast, stable log(sigmoid(x)) = min(x,0) - log(1 + exp(-|x|))
__device__ __forceinline__ float log_sigmoid_fast(float x) {
    return fminf(x, 0.0f) - __logf(1.0f + __expf(-fabsf(x)));
}

__global__ __launch_bounds__(128) void skipgram_kernel(
    const int* __restrict__ target,
    const int* __restrict__ context,
    const int* __restrict__ negs,
    const float* __restrict__ in_embed,
    const float* __restrict__ out_embed,
    float* __restrict__ out)
{
    const int lane = threadIdx.x & 31;
    const int warp_in_block = threadIdx.x >> 5;
    // grid is exact: 16384 rows / (4 warps/block) = 4096 blocks, no bounds check.
    const int b = blockIdx.x * 4 + warp_in_block;

    // One coalesced index load for the whole warp:
    // lane 0..19 -> neg index k=lane ; lane 20..31 -> context index (uniform).
    const int* nb = negs + (size_t)b * K_NEG;
    const int idx = (lane < K_NEG) ? __ldg(nb + lane) : __ldg(context + b);

    // Each lane owns 4 consecutive floats of the 128-float row.
    const float4 tv = reinterpret_cast<const float4*>(
        in_embed + (size_t)__ldg(target + b) * DIM)[lane];

    // v[k] = this lane's partial dot for value k.
    // k in [0,20): negative scores; k == 20: positive; k > 20: don't-care.
    float v[32];

    #pragma unroll
    for (int k = 0; k <= K_NEG; k++) {
        const int row = __shfl_sync(0xffffffffu, idx, k);
        const float4 nv = reinterpret_cast<const float4*>(
            out_embed + (size_t)row * DIM)[lane];
        v[k] = tv.x * nv.x + tv.y * nv.y + tv.z * nv.z + tv.w * nv.w;
    }
    #pragma unroll
    for (int j = K_NEG + 1; j < 32; j++) v[j] = v[K_NEG];  // cheap pad (reg copy)

    // Packed butterfly transpose-reduce: after 5 stages, v[0] on lane L holds
    // the fully lane-summed score for value L. 31 shuffles total.
    #pragma unroll
    for (int i = 0; i < 5; i++) {
        const int off = 1 << i;
        const bool par = (lane >> i) & 1;
        const int n = 32 >> i;
        #pragma unroll
        for (int j = 0; j < n / 2; j++) {
            const float a = v[2 * j];
            const float c = v[2 * j + 1];
            const float send = par ? a : c;
            const float keep = par ? c : a;
            const float got = __shfl_xor_sync(0xffffffffu, send, off);
            v[j] = keep + got;
        }
    }

    const float s = v[0];                    // score for value index == lane
    const float x = (lane == K_NEG) ? s : -s;
    float contrib = (lane <= K_NEG) ? log_sigmoid_fast(x) : 0.0f;

    // Sum the 21 per-lane loss terms of this row, then block-reduce.
    contrib = warp_sum(contrib);

    __shared__ float smem[4];
    if (lane == 0) smem[warp_in_block] = contrib;
    __syncthreads();

    if (threadIdx.x == 0) {
        float acc = smem[0] + smem[1] + smem[2] + smem[3];
        atomicAdd(out, -acc * (1.0f / (float)B_SIZE));
    }
}

extern "C" void kernel_launch(void* const* d_in, const int* in_sizes, int n_in,
                              void* d_out, int out_size) {
    const int*   target    = (const int*)d_in[0];
    const int*   context   = (const int*)d_in[1];
    const int*   negs      = (const int*)d_in[2];
    const float* in_embed  = (const float*)d_in[3];
    const float* out_embed = (const float*)d_in[4];
    float*       out       = (float*)d_out;

    zero_out_kernel<<<1, 32>>>(out, out_size);

    // 4 warps per block, one batch row per warp; 16384/4 = 4096 blocks exact.
    skipgram_kernel<<<B_SIZE / 4, 128>>>(
        target, context, negs, in_embed, out_embed, out);
}